// round 8
// baseline (speedup 1.0000x reference)
#include <cuda_runtime.h>
#include <math.h>

// Problem constants
#define H     1536
#define H3    4608          // 3*H
#define HV    128           // vocab
#define ML    128           // max_length
#define AROWS 129           // ML+1 attention rows
#define MPAD  132           // padded row stride for 129-wide matrices
#define GRID  148
#define BLOCK 1024

// ---------------- device scratch (no allocations allowed) ----------------
__device__ __align__(16) float g_h[2][H];             // ping-pong hidden state
__device__ __align__(16) float g_encout[AROWS * H];   // encoder_outputs (129 x 1536)
__device__ __align__(16) float g_gh[H3];              // dec_Whh @ h + bhh
__device__ __align__(16) float g_attnh[AROWS];        // attn h-half logits
__device__ __align__(16) float g_o[HV];               // output logits
__device__ __align__(16) float g_x[H];                // relu(comb) input to dec GRU
__device__ __align__(16) float g_M[H * MPAD];         // comb_W_ctx @ encout^T  (1536 x 129)
__device__ __align__(16) float g_attE[HV * MPAD];     // attn_W_emb @ emb_dec^T + attn_b
__device__ __align__(16) float g_combE[HV * H];       // comb_W_emb @ emb_dec^T + comb_b
__device__ unsigned g_bar;                            // grid barrier (monotonic)

// ---------------- grid-wide barrier (all 148 CTAs resident: 1 CTA/SM) ----
__device__ __forceinline__ void grid_sync() {
    __syncthreads();
    if (threadIdx.x == 0) {
        __threadfence();
        unsigned nb  = gridDim.x;
        unsigned old = atomicAdd(&g_bar, 1u);
        unsigned target = old - (old % nb) + nb;   // next multiple of nb
        while ((int)(*(volatile unsigned*)&g_bar - target) < 0) { }
        __threadfence();
    }
    __syncthreads();
}

// ---------------- warp helpers ----------------
__device__ __forceinline__ float wredu(float v) {
#pragma unroll
    for (int o = 16; o; o >>= 1) v += __shfl_xor_sync(0xffffffffu, v, o);
    return v;
}

// argmax with first-index tie-break (matches jnp.argmax)
__device__ __forceinline__ void wargmax(float& m, int& am) {
#pragma unroll
    for (int o = 16; o; o >>= 1) {
        float m2 = __shfl_xor_sync(0xffffffffu, m, o);
        int   a2 = __shfl_xor_sync(0xffffffffu, am, o);
        if (m2 > m || (m2 == m && a2 < am)) { m = m2; am = a2; }
    }
}

// per-lane partial dot of a 1536-length row with a 1536-length vector
__device__ __forceinline__ float dot1536(const float* __restrict__ w,
                                         const float* __restrict__ x, int lane) {
    const float4* w4 = (const float4*)w;
    const float4* x4 = (const float4*)x;
    float s = 0.f;
#pragma unroll 4
    for (int i = 0; i < 12; i++) {
        float4 a = w4[lane + 32 * i];
        float4 b = x4[lane + 32 * i];
        s = fmaf(a.x, b.x, s);
        s = fmaf(a.y, b.y, s);
        s = fmaf(a.z, b.z, s);
        s = fmaf(a.w, b.w, s);
    }
    return s;
}

// one weight row vs 8 vectors (precompute GEMMs; vectors L1-resident per tile)
__device__ __forceinline__ void dot8(const float* __restrict__ w,
                                     const float4* p0, const float4* p1,
                                     const float4* p2, const float4* p3,
                                     const float4* p4, const float4* p5,
                                     const float4* p6, const float4* p7,
                                     int lane, float* r) {
    const float4* w4 = (const float4*)w;
    float s0=0.f,s1=0.f,s2=0.f,s3=0.f,s4=0.f,s5=0.f,s6=0.f,s7=0.f;
#pragma unroll 2
    for (int i = 0; i < 12; i++) {
        int idx = lane + 32 * i;
        float4 a = w4[idx];
        float4 b;
        b = p0[idx]; s0 = fmaf(a.x,b.x,s0); s0 = fmaf(a.y,b.y,s0); s0 = fmaf(a.z,b.z,s0); s0 = fmaf(a.w,b.w,s0);
        b = p1[idx]; s1 = fmaf(a.x,b.x,s1); s1 = fmaf(a.y,b.y,s1); s1 = fmaf(a.z,b.z,s1); s1 = fmaf(a.w,b.w,s1);
        b = p2[idx]; s2 = fmaf(a.x,b.x,s2); s2 = fmaf(a.y,b.y,s2); s2 = fmaf(a.z,b.z,s2); s2 = fmaf(a.w,b.w,s2);
        b = p3[idx]; s3 = fmaf(a.x,b.x,s3); s3 = fmaf(a.y,b.y,s3); s3 = fmaf(a.z,b.z,s3); s3 = fmaf(a.w,b.w,s3);
        b = p4[idx]; s4 = fmaf(a.x,b.x,s4); s4 = fmaf(a.y,b.y,s4); s4 = fmaf(a.z,b.z,s4); s4 = fmaf(a.w,b.w,s4);
        b = p5[idx]; s5 = fmaf(a.x,b.x,s5); s5 = fmaf(a.y,b.y,s5); s5 = fmaf(a.z,b.z,s5); s5 = fmaf(a.w,b.w,s5);
        b = p6[idx]; s6 = fmaf(a.x,b.x,s6); s6 = fmaf(a.y,b.y,s6); s6 = fmaf(a.z,b.z,s6); s6 = fmaf(a.w,b.w,s6);
        b = p7[idx]; s7 = fmaf(a.x,b.x,s7); s7 = fmaf(a.y,b.y,s7); s7 = fmaf(a.z,b.z,s7); s7 = fmaf(a.w,b.w,s7);
    }
    r[0]=s0; r[1]=s1; r[2]=s2; r[3]=s3; r[4]=s4; r[5]=s5; r[6]=s6; r[7]=s7;
}

__device__ __forceinline__ float sigm(float x) { return 1.f / (1.f + expf(-x)); }

// ---------------- persistent kernel ----------------
__global__ __launch_bounds__(BLOCK, 1)
void seq2seq_kernel(const int* __restrict__ input, int L,
                    const float* __restrict__ emb_enc,
                    const float* __restrict__ enc_Wih, const float* __restrict__ enc_Whh,
                    const float* __restrict__ enc_bih, const float* __restrict__ enc_bhh,
                    const float* __restrict__ emb_dec,
                    const float* __restrict__ attn_W, const float* __restrict__ attn_b,
                    const float* __restrict__ comb_W, const float* __restrict__ comb_b,
                    const float* __restrict__ dec_Wih, const float* __restrict__ dec_Whh,
                    const float* __restrict__ dec_bih, const float* __restrict__ dec_bhh,
                    const float* __restrict__ out_W, const float* __restrict__ out_b,
                    float* __restrict__ out, int write_tok)
{
    const int tid  = threadIdx.x;
    const int lane = tid & 31;
    const int wid  = tid >> 5;
    // interleave warp ids across blocks so every phase keeps all SMs busy
    const int WGID = wid * gridDim.x + blockIdx.x;
    const int NW   = gridDim.x * (blockDim.x >> 5);

    __shared__ float s_w[AROWS];     // unnormalized softmax weights
    __shared__ float s_S, s_lse;
    __shared__ int   s_tok;

    // ---- init: zero h0 and the unused tail rows of encoder_outputs ----
    {
        int gt = blockIdx.x * blockDim.x + tid;
        int NT = gridDim.x * blockDim.x;
        for (int i = gt; i < H; i += NT) g_h[0][i] = 0.f;
        for (int i = L * H + gt; i < AROWS * H; i += NT) g_encout[i] = 0.f;
    }

    // ---- P_E (tiled): attE/combE = [attn_W_e; comb_W_e] @ emb_dec^T + bias ----
    // One row per warp (L1-resident across tiles); 8 shared emb vectors per tile.
    {
        int r = WGID;
        const float* w = attn_W; float bias = 0.f; int rc = 0; bool isA = true;
        bool valid = (r < AROWS + H);
        if (r < AROWS)  { w = attn_W + r * (2 * H); bias = attn_b[r]; }
        else if (valid) { rc = r - AROWS; w = comb_W + rc * (2 * H); bias = comb_b[rc]; isA = false; }
        const float4* E4 = (const float4*)emb_dec;
        for (int tile = 0; tile < HV / 8; tile++) {
            if (valid) {
                int v0 = tile * 8;
                float s[8];
                dot8(w, E4 + (v0+0)*384, E4 + (v0+1)*384, E4 + (v0+2)*384, E4 + (v0+3)*384,
                        E4 + (v0+4)*384, E4 + (v0+5)*384, E4 + (v0+6)*384, E4 + (v0+7)*384,
                     lane, s);
#pragma unroll
                for (int q = 0; q < 8; q++) s[q] = wredu(s[q]);
                if (lane == 0) {
#pragma unroll
                    for (int q = 0; q < 8; q++) {
                        if (isA) g_attE[(v0+q) * MPAD + r] = s[q] + bias;
                        else     g_combE[(v0+q) * H + rc]  = s[q] + bias;
                    }
                }
            }
            __syncthreads();
        }
    }
    grid_sync();

    int cur = 0;

    // =========================== ENCODER ===========================
    for (int t = 0; t < L; t++) {
        const float* x    = emb_enc + input[t] * H;
        const float* hold = g_h[cur];
        float*       hnew = g_h[cur ^ 1];

        for (int j = WGID; j < H; j += NW) {
            float ar = dot1536(enc_Wih + j * H,            x, lane);
            float az = dot1536(enc_Wih + (H + j) * H,      x, lane);
            float an = dot1536(enc_Wih + (2 * H + j) * H,  x, lane);
            float br = dot1536(enc_Whh + j * H,            hold, lane);
            float bz = dot1536(enc_Whh + (H + j) * H,      hold, lane);
            float bn = dot1536(enc_Whh + (2 * H + j) * H,  hold, lane);
            float rp  = wredu(ar + br);
            float zp  = wredu(az + bz);
            float anr = wredu(an);
            float bnr = wredu(bn);
            if (lane == 0) {
                float r  = sigm(rp + enc_bih[j] + enc_bhh[j]);
                float z  = sigm(zp + enc_bih[H + j] + enc_bhh[H + j]);
                float n  = tanhf(anr + enc_bih[2 * H + j] + r * (bnr + enc_bhh[2 * H + j]));
                float hv = (1.f - z) * n + z * hold[j];
                hnew[j] = hv;
                g_encout[t * H + j] = hv;
            }
        }
        grid_sync();
        cur ^= 1;
    }

    // ---- P_M (tiled): M[i][k] = comb_W_ctx[i,:] . encout[k,:] ----
    {
        int r = WGID;
        const float* w = (r < H) ? comb_W + r * (2 * H) + H : comb_W;
        const float4* EO = (const float4*)g_encout;
        for (int tile = 0; tile < 17; tile++) {
            if (r < H) {
                int k0 = tile * 8;
                float s[8];
                dot8(w, EO + min(k0+0, AROWS-1)*384, EO + min(k0+1, AROWS-1)*384,
                        EO + min(k0+2, AROWS-1)*384, EO + min(k0+3, AROWS-1)*384,
                        EO + min(k0+4, AROWS-1)*384, EO + min(k0+5, AROWS-1)*384,
                        EO + min(k0+6, AROWS-1)*384, EO + min(k0+7, AROWS-1)*384,
                     lane, s);
#pragma unroll
                for (int q = 0; q < 8; q++) s[q] = wredu(s[q]);
                if (lane == 0) {
#pragma unroll
                    for (int q = 0; q < 8; q++)
                        if (k0 + q < AROWS) g_M[r * MPAD + k0 + q] = s[q];
                }
            }
            __syncthreads();
        }
    }
    grid_sync();

    // =========================== DECODER ===========================
    for (int t = 0; t < ML; t++) {
        const float* h = g_h[cur];

        // --- P1: gh = Whh.h+bhh (4608) || out logits (128) || attn_h (129) ---
        for (int task = WGID; task < H3 + HV + AROWS; task += NW) {
            if (task < H3) {
                float s = wredu(dot1536(dec_Whh + task * H, h, lane));
                if (lane == 0) g_gh[task] = s + dec_bhh[task];
            } else if (task < H3 + HV) {
                int v = task - H3;
                float s = wredu(dot1536(out_W + v * H, h, lane));
                if (lane == 0) g_o[v] = s + out_b[v];
            } else {
                int k = task - H3 - HV;
                float s = wredu(dot1536(attn_W + k * (2 * H) + H, h, lane));
                if (lane == 0) g_attnh[k] = s;
            }
        }
        grid_sync();

        // --- P2: token select, emit row t-1, softmax, x rows ---
        if (wid == 0) {
            int tok; float lse;
            if (t == 0) { tok = 0; lse = 0.f; }
            else {
                float m = -1e30f; int am = HV;
                for (int v = lane; v < HV; v += 32) {
                    float ov = g_o[v];
                    if (ov > m) { m = ov; am = v; }
                }
                wargmax(m, am);
                float e = 0.f;
                for (int v = lane; v < HV; v += 32) e += expf(g_o[v] - m);
                e = wredu(e);
                lse = m + logf(e);
                tok = am;
            }
            if (lane == 0) { s_tok = tok; s_lse = lse; }
        }
        __syncthreads();
        const int tok = s_tok;
        if (t > 0 && blockIdx.x == 0 && wid == 1) {
            for (int v = lane; v < HV; v += 32) out[(t - 1) * HV + v] = g_o[v] - s_lse;
            if (lane == 0 && write_tok) out[ML * HV + (t - 1)] = (float)tok;
        }
        if (wid == 0) {
            const float* aE = g_attE + tok * MPAD;
            float m = -1e30f;
            for (int k = lane; k < AROWS; k += 32) m = fmaxf(m, aE[k] + g_attnh[k]);
#pragma unroll
            for (int o = 16; o; o >>= 1) m = fmaxf(m, __shfl_xor_sync(0xffffffffu, m, o));
            float ssum = 0.f;
            for (int k = lane; k < AROWS; k += 32) {
                float e = expf(aE[k] + g_attnh[k] - m);
                s_w[k] = e;
                ssum += e;
            }
            ssum = wredu(ssum);
            if (lane == 0) s_S = ssum;
        }
        __syncthreads();
        {
            const float invS = 1.f / s_S;
            const float* cE = g_combE + tok * H;
            for (int i = WGID; i < H; i += NW) {
                const float* Mr = g_M + i * MPAD;
                float s = 0.f;
                for (int k = lane; k < AROWS; k += 32) s = fmaf(s_w[k], Mr[k], s);
                s = wredu(s);
                if (lane == 0) g_x[i] = fmaxf(0.f, cE[i] + s * invS);
            }
        }
        grid_sync();

        // --- P3: gi = dec_Wih @ x, gates -> h' ---
        {
            const float* hold = h;
            float* hnew = g_h[cur ^ 1];
            for (int j = WGID; j < H; j += NW) {
                float ar = wredu(dot1536(dec_Wih + j * H,           g_x, lane));
                float az = wredu(dot1536(dec_Wih + (H + j) * H,     g_x, lane));
                float an = wredu(dot1536(dec_Wih + (2 * H + j) * H, g_x, lane));
                if (lane == 0) {
                    float r = sigm(ar + dec_bih[j]          + g_gh[j]);
                    float z = sigm(az + dec_bih[H + j]      + g_gh[H + j]);
                    float n = tanhf(an + dec_bih[2 * H + j] + r * g_gh[2 * H + j]);
                    hnew[j] = (1.f - z) * n + z * hold[j];
                }
            }
        }
        grid_sync();
        cur ^= 1;
    }

    // ---- final logits for row ML-1 ----
    {
        const float* hf = g_h[cur];
        for (int v = WGID; v < HV; v += NW) {
            float s = wredu(dot1536(out_W + v * H, hf, lane));
            if (lane == 0) g_o[v] = s + out_b[v];
        }
    }
    grid_sync();

    if (blockIdx.x == 0 && wid == 0) {
        float m = -1e30f; int am = HV;
        for (int v = lane; v < HV; v += 32) {
            float ov = g_o[v];
            if (ov > m) { m = ov; am = v; }
        }
        wargmax(m, am);
        float e = 0.f;
        for (int v = lane; v < HV; v += 32) e += expf(g_o[v] - m);
        e = wredu(e);
        float lse = m + logf(e);
        for (int v = lane; v < HV; v += 32) out[(ML - 1) * HV + v] = g_o[v] - lse;
        if (lane == 0 && write_tok) out[ML * HV + (ML - 1)] = (float)am;
    }
}

// ---------------- launch ----------------
extern "C" void kernel_launch(void* const* d_in, const int* in_sizes, int n_in,
                              void* d_out, int out_size) {
    const int*   input   = (const int*)  d_in[0];
    const int    L       = in_sizes[0];
    // d_in[1] = max_length scalar (compile-time ML=128)
    const float* emb_enc = (const float*)d_in[2];
    const float* enc_Wih = (const float*)d_in[3];
    const float* enc_Whh = (const float*)d_in[4];
    const float* enc_bih = (const float*)d_in[5];
    const float* enc_bhh = (const float*)d_in[6];
    const float* emb_dec = (const float*)d_in[7];
    const float* attn_W  = (const float*)d_in[8];
    const float* attn_b  = (const float*)d_in[9];
    const float* comb_W  = (const float*)d_in[10];
    const float* comb_b  = (const float*)d_in[11];
    const float* dec_Wih = (const float*)d_in[12];
    const float* dec_Whh = (const float*)d_in[13];
    const float* dec_bih = (const float*)d_in[14];
    const float* dec_bhh = (const float*)d_in[15];
    const float* out_W   = (const float*)d_in[16];
    const float* out_b   = (const float*)d_in[17];

    int write_tok = (out_size >= ML * HV + ML) ? 1 : 0;

    seq2seq_kernel<<<GRID, BLOCK>>>(input, L, emb_enc,
                                    enc_Wih, enc_Whh, enc_bih, enc_bhh,
                                    emb_dec, attn_W, attn_b, comb_W, comb_b,
                                    dec_Wih, dec_Whh, dec_bih, dec_bhh,
                                    out_W, out_b,
                                    (float*)d_out, write_tok);
}

// round 11
// speedup vs baseline: 1.3563x; 1.3563x over previous
#include <cuda_runtime.h>
#include <cuda_fp16.h>
#include <math.h>

// Problem constants
#define H     1536
#define H3    4608          // 3*H
#define HV    128           // vocab
#define ML    128           // max_length
#define AROWS 129           // ML+1 attention rows
#define MPAD  132           // padded row stride for 129-wide matrices
#define GRID  148
#define BLOCK 1024

// ---------------- device scratch (no allocations allowed) ----------------
__device__ __align__(16) float g_h[2][H];             // ping-pong hidden state
__device__ __align__(16) float g_encout[AROWS * H];   // encoder_outputs (129 x 1536)
__device__ __align__(16) float g_gh[H3];              // dec_Whh @ h + bhh
__device__ __align__(16) float g_attnh[AROWS];        // attn h-half logits
__device__ __align__(16) float g_o[HV];               // output logits
__device__ __align__(16) float g_x[H];                // relu(comb) input to dec GRU
__device__ __align__(16) float g_M[H * MPAD];         // comb_W_ctx @ encout^T
__device__ __align__(16) float g_attE[HV * MPAD];     // attn_W_emb @ emb_dec^T + attn_b
__device__ __align__(16) float g_combE[HV * H];       // comb_W_emb @ emb_dec^T + comb_b
__device__ unsigned g_bar;                            // grid barrier (monotonic)

// fp16 weight copies (converted by pre-kernels each replay; deterministic)
__device__ __align__(16) __half g_eWih_h[(size_t)H3 * H];
__device__ __align__(16) __half g_eWhh_h[(size_t)H3 * H];
__device__ __align__(16) __half g_dWih_h[(size_t)H3 * H];
__device__ __align__(16) __half g_dWhh_h[(size_t)H3 * H];
__device__ __align__(16) __half g_outW_h[HV * H];
__device__ __align__(16) __half g_attnWh_h[AROWS * H];   // attn_W h-half

// ---------------- conversion pre-kernels ----------------
__global__ void cvt_kernel(const float4* __restrict__ src, int n4, int which) {
    __half2* dst;
    switch (which) {
        case 0: dst = (__half2*)g_eWih_h; break;
        case 1: dst = (__half2*)g_eWhh_h; break;
        case 2: dst = (__half2*)g_dWih_h; break;
        case 3: dst = (__half2*)g_dWhh_h; break;
        default: dst = (__half2*)g_outW_h; break;
    }
    int i  = blockIdx.x * blockDim.x + threadIdx.x;
    int st = gridDim.x * blockDim.x;
    for (; i < n4; i += st) {
        float4 v = src[i];
        dst[2 * i]     = __floats2half2_rn(v.x, v.y);
        dst[2 * i + 1] = __floats2half2_rn(v.z, v.w);
    }
}

// attn_W h-half (row stride 2H, offset H)
__global__ void cvt_attn_kernel(const float* __restrict__ attn_W) {
    int i  = blockIdx.x * blockDim.x + threadIdx.x;
    int st = gridDim.x * blockDim.x;
    int n4 = AROWS * H / 4;
    __half2* dst = (__half2*)g_attnWh_h;
    for (; i < n4; i += st) {
        int k = (i * 4) / H, c = (i * 4) % H;
        const float4 v = *(const float4*)(attn_W + k * (2 * H) + H + c);
        dst[2 * i]     = __floats2half2_rn(v.x, v.y);
        dst[2 * i + 1] = __floats2half2_rn(v.z, v.w);
    }
}

// ---------------- grid-wide barrier (1 CTA/SM) with backoff ----------------
__device__ __forceinline__ void grid_sync() {
    __syncthreads();
    if (threadIdx.x == 0) {
        __threadfence();
        unsigned nb  = gridDim.x;
        unsigned old = atomicAdd(&g_bar, 1u);
        unsigned target = old - (old % nb) + nb;   // next multiple of nb
        while ((int)(*(volatile unsigned*)&g_bar - target) < 0) {
            __nanosleep(64);
        }
        __threadfence();
    }
    __syncthreads();
}

// ---------------- warp helpers ----------------
__device__ __forceinline__ float wredu(float v) {
#pragma unroll
    for (int o = 16; o; o >>= 1) v += __shfl_xor_sync(0xffffffffu, v, o);
    return v;
}

// argmax with first-index tie-break (matches jnp.argmax)
__device__ __forceinline__ void wargmax(float& m, int& am) {
#pragma unroll
    for (int o = 16; o; o >>= 1) {
        float m2 = __shfl_xor_sync(0xffffffffu, m, o);
        int   a2 = __shfl_xor_sync(0xffffffffu, am, o);
        if (m2 > m || (m2 == m && a2 < am)) { m = m2; am = a2; }
    }
}

__device__ __forceinline__ float sigm(float x) { return 1.f / (1.f + expf(-x)); }

// 8 fp16 weights (one uint4) against 8 fp32 vector elems; register-safe casts
__device__ __forceinline__ float acc8(uint4 A, float4 b0, float4 b1, float s) {
    __half2 h0 = *reinterpret_cast<const __half2*>(&A.x);
    __half2 h1 = *reinterpret_cast<const __half2*>(&A.y);
    __half2 h2 = *reinterpret_cast<const __half2*>(&A.z);
    __half2 h3 = *reinterpret_cast<const __half2*>(&A.w);
    float2 f;
    f = __half22float2(h0); s = fmaf(f.x, b0.x, s); s = fmaf(f.y, b0.y, s);
    f = __half22float2(h1); s = fmaf(f.x, b0.z, s); s = fmaf(f.y, b0.w, s);
    f = __half22float2(h2); s = fmaf(f.x, b1.x, s); s = fmaf(f.y, b1.y, s);
    f = __half22float2(h3); s = fmaf(f.x, b1.z, s); s = fmaf(f.y, b1.w, s);
    return s;
}

// fp16 weight row . fp32 vector
__device__ __forceinline__ float dot1536h(const __half* __restrict__ w,
                                          const float* __restrict__ x, int lane) {
    const uint4*  w8 = (const uint4*)w;
    const float4* x4 = (const float4*)x;
    float s = 0.f;
#pragma unroll
    for (int i = 0; i < 6; i++) {
        int idx = lane + 32 * i;
        s = acc8(w8[idx], x4[2 * idx], x4[2 * idx + 1], s);
    }
    return s;
}

// three fp16 rows vs one fp32 vector (shared vector loads)
__device__ __forceinline__ void dot3h(const __half* __restrict__ w0,
                                      const __half* __restrict__ w1,
                                      const __half* __restrict__ w2,
                                      const float* __restrict__ x,
                                      int lane, float* r) {
    const uint4*  a0 = (const uint4*)w0;
    const uint4*  a1 = (const uint4*)w1;
    const uint4*  a2 = (const uint4*)w2;
    const float4* x4 = (const float4*)x;
    float s0 = 0.f, s1 = 0.f, s2 = 0.f;
#pragma unroll
    for (int i = 0; i < 6; i++) {
        int idx = lane + 32 * i;
        float4 b0 = x4[2 * idx];
        float4 b1 = x4[2 * idx + 1];
        s0 = acc8(a0[idx], b0, b1, s0);
        s1 = acc8(a1[idx], b0, b1, s1);
        s2 = acc8(a2[idx], b0, b1, s2);
    }
    r[0] = s0; r[1] = s1; r[2] = s2;
}

// one fp32 weight row vs 8 fp32 vectors (precompute GEMMs)
__device__ __forceinline__ void dot8(const float* __restrict__ w,
                                     const float4* p0, const float4* p1,
                                     const float4* p2, const float4* p3,
                                     const float4* p4, const float4* p5,
                                     const float4* p6, const float4* p7,
                                     int lane, float* r) {
    const float4* w4 = (const float4*)w;
    float s0=0.f,s1=0.f,s2=0.f,s3=0.f,s4=0.f,s5=0.f,s6=0.f,s7=0.f;
#pragma unroll 2
    for (int i = 0; i < 12; i++) {
        int idx = lane + 32 * i;
        float4 a = w4[idx];
        float4 b;
        b = p0[idx]; s0 = fmaf(a.x,b.x,s0); s0 = fmaf(a.y,b.y,s0); s0 = fmaf(a.z,b.z,s0); s0 = fmaf(a.w,b.w,s0);
        b = p1[idx]; s1 = fmaf(a.x,b.x,s1); s1 = fmaf(a.y,b.y,s1); s1 = fmaf(a.z,b.z,s1); s1 = fmaf(a.w,b.w,s1);
        b = p2[idx]; s2 = fmaf(a.x,b.x,s2); s2 = fmaf(a.y,b.y,s2); s2 = fmaf(a.z,b.z,s2); s2 = fmaf(a.w,b.w,s2);
        b = p3[idx]; s3 = fmaf(a.x,b.x,s3); s3 = fmaf(a.y,b.y,s3); s3 = fmaf(a.z,b.z,s3); s3 = fmaf(a.w,b.w,s3);
        b = p4[idx]; s4 = fmaf(a.x,b.x,s4); s4 = fmaf(a.y,b.y,s4); s4 = fmaf(a.z,b.z,s4); s4 = fmaf(a.w,b.w,s4);
        b = p5[idx]; s5 = fmaf(a.x,b.x,s5); s5 = fmaf(a.y,b.y,s5); s5 = fmaf(a.z,b.z,s5); s5 = fmaf(a.w,b.w,s5);
        b = p6[idx]; s6 = fmaf(a.x,b.x,s6); s6 = fmaf(a.y,b.y,s6); s6 = fmaf(a.z,b.z,s6); s6 = fmaf(a.w,b.w,s6);
        b = p7[idx]; s7 = fmaf(a.x,b.x,s7); s7 = fmaf(a.y,b.y,s7); s7 = fmaf(a.z,b.z,s7); s7 = fmaf(a.w,b.w,s7);
    }
    r[0]=s0; r[1]=s1; r[2]=s2; r[3]=s3; r[4]=s4; r[5]=s5; r[6]=s6; r[7]=s7;
}

// ---------------- persistent kernel ----------------
__global__ __launch_bounds__(BLOCK, 1)
void seq2seq_kernel(const int* __restrict__ input, int L,
                    const float* __restrict__ emb_enc,
                    const float* __restrict__ enc_bih, const float* __restrict__ enc_bhh,
                    const float* __restrict__ emb_dec,
                    const float* __restrict__ attn_W, const float* __restrict__ attn_b,
                    const float* __restrict__ comb_W, const float* __restrict__ comb_b,
                    const float* __restrict__ dec_bih, const float* __restrict__ dec_bhh,
                    const float* __restrict__ out_b,
                    float* __restrict__ out, int write_tok)
{
    const int tid  = threadIdx.x;
    const int lane = tid & 31;
    const int wid  = tid >> 5;
    const int WGID = wid * gridDim.x + blockIdx.x;
    const int NW   = gridDim.x * (blockDim.x >> 5);

    __shared__ float s_w[AROWS];     // unnormalized softmax weights
    __shared__ float s_S, s_lse;
    __shared__ int   s_tok;

    // ---- init: zero h0 and the unused tail rows of encoder_outputs ----
    {
        int gt = blockIdx.x * blockDim.x + tid;
        int NT = gridDim.x * blockDim.x;
        for (int i = gt; i < H; i += NT) g_h[0][i] = 0.f;
        for (int i = L * H + gt; i < AROWS * H; i += NT) g_encout[i] = 0.f;
    }

    // ---- P_E (tiled): attE/combE = [attn_W_e; comb_W_e] @ emb_dec^T + bias ----
    {
        int r = WGID;
        const float* w = attn_W; float bias = 0.f; int rc = 0; bool isA = true;
        bool valid = (r < AROWS + H);
        if (r < AROWS)  { w = attn_W + r * (2 * H); bias = attn_b[r]; }
        else if (valid) { rc = r - AROWS; w = comb_W + rc * (2 * H); bias = comb_b[rc]; isA = false; }
        const float4* E4 = (const float4*)emb_dec;
        for (int tile = 0; tile < HV / 8; tile++) {
            if (valid) {
                int v0 = tile * 8;
                float s[8];
                dot8(w, E4 + (v0+0)*384, E4 + (v0+1)*384, E4 + (v0+2)*384, E4 + (v0+3)*384,
                        E4 + (v0+4)*384, E4 + (v0+5)*384, E4 + (v0+6)*384, E4 + (v0+7)*384,
                     lane, s);
#pragma unroll
                for (int q = 0; q < 8; q++) s[q] = wredu(s[q]);
                if (lane == 0) {
#pragma unroll
                    for (int q = 0; q < 8; q++) {
                        if (isA) g_attE[(v0+q) * MPAD + r] = s[q] + bias;
                        else     g_combE[(v0+q) * H + rc]  = s[q] + bias;
                    }
                }
            }
            __syncthreads();
        }
    }
    grid_sync();

    int cur = 0;

    // =========================== ENCODER ===========================
    for (int t = 0; t < L; t++) {
        const float* x    = emb_enc + __ldg(&input[t]) * H;
        const float* hold = g_h[cur];
        float*       hnew = g_h[cur ^ 1];

        for (int j = WGID; j < H; j += NW) {
            float gi[3], gh3[3];
            dot3h(g_eWih_h + (size_t)j * H, g_eWih_h + (size_t)(H + j) * H,
                  g_eWih_h + (size_t)(2 * H + j) * H, x, lane, gi);
            dot3h(g_eWhh_h + (size_t)j * H, g_eWhh_h + (size_t)(H + j) * H,
                  g_eWhh_h + (size_t)(2 * H + j) * H, hold, lane, gh3);
            float rp  = wredu(gi[0] + gh3[0]);
            float zp  = wredu(gi[1] + gh3[1]);
            float anr = wredu(gi[2]);
            float bnr = wredu(gh3[2]);
            if (lane == 0) {
                float r  = sigm(rp + enc_bih[j] + enc_bhh[j]);
                float z  = sigm(zp + enc_bih[H + j] + enc_bhh[H + j]);
                float n  = tanhf(anr + enc_bih[2 * H + j] + r * (bnr + enc_bhh[2 * H + j]));
                float hv = (1.f - z) * n + z * hold[j];
                hnew[j] = hv;
                g_encout[t * H + j] = hv;
            }
        }
        grid_sync();
        cur ^= 1;
    }

    // ---- P_M (tiled): M[i][k] = comb_W_ctx[i,:] . encout[k,:] ----
    {
        int r = WGID;
        const float* w = (r < H) ? comb_W + r * (2 * H) + H : comb_W;
        const float4* EO = (const float4*)g_encout;
        for (int tile = 0; tile < 17; tile++) {
            if (r < H) {
                int k0 = tile * 8;
                float s[8];
                dot8(w, EO + min(k0+0, AROWS-1)*384, EO + min(k0+1, AROWS-1)*384,
                        EO + min(k0+2, AROWS-1)*384, EO + min(k0+3, AROWS-1)*384,
                        EO + min(k0+4, AROWS-1)*384, EO + min(k0+5, AROWS-1)*384,
                        EO + min(k0+6, AROWS-1)*384, EO + min(k0+7, AROWS-1)*384,
                     lane, s);
#pragma unroll
                for (int q = 0; q < 8; q++) s[q] = wredu(s[q]);
                if (lane == 0) {
#pragma unroll
                    for (int q = 0; q < 8; q++)
                        if (k0 + q < AROWS) g_M[r * MPAD + k0 + q] = s[q];
                }
            }
            __syncthreads();
        }
    }
    grid_sync();

    // =========================== DECODER ===========================
    for (int t = 0; t < ML; t++) {
        const float* h = g_h[cur];

        // --- P1: gh = Whh.h+bhh (4608) || out logits (128) || attn_h (129) ---
        for (int task = WGID; task < H3 + HV + AROWS; task += NW) {
            if (task < H3) {
                float s = wredu(dot1536h(g_dWhh_h + (size_t)task * H, h, lane));
                if (lane == 0) g_gh[task] = s + dec_bhh[task];
            } else if (task < H3 + HV) {
                int v = task - H3;
                float s = wredu(dot1536h(g_outW_h + v * H, h, lane));
                if (lane == 0) g_o[v] = s + out_b[v];
            } else {
                int k = task - H3 - HV;
                float s = wredu(dot1536h(g_attnWh_h + k * H, h, lane));
                if (lane == 0) g_attnh[k] = s;
            }
        }
        grid_sync();

        // --- P2: token select, emit row t-1, softmax, x rows ---
        if (wid == 0) {
            int tok; float lse;
            if (t == 0) { tok = 0; lse = 0.f; }
            else {
                float m = -1e30f; int am = HV;
                for (int v = lane; v < HV; v += 32) {
                    float ov = g_o[v];
                    if (ov > m) { m = ov; am = v; }
                }
                wargmax(m, am);
                float e = 0.f;
                for (int v = lane; v < HV; v += 32) e += expf(g_o[v] - m);
                e = wredu(e);
                lse = m + logf(e);
                tok = am;
            }
            if (lane == 0) { s_tok = tok; s_lse = lse; }
        }
        __syncthreads();
        const int tok = s_tok;
        if (t > 0 && blockIdx.x == 0 && wid == 1) {
            for (int v = lane; v < HV; v += 32) out[(t - 1) * HV + v] = g_o[v] - s_lse;
            if (lane == 0 && write_tok) out[ML * HV + (t - 1)] = (float)tok;
        }
        if (wid == 0) {
            const float* aE = g_attE + tok * MPAD;
            float m = -1e30f;
            for (int k = lane; k < AROWS; k += 32) m = fmaxf(m, aE[k] + g_attnh[k]);
#pragma unroll
            for (int o = 16; o; o >>= 1) m = fmaxf(m, __shfl_xor_sync(0xffffffffu, m, o));
            float ssum = 0.f;
            for (int k = lane; k < AROWS; k += 32) {
                float e = expf(aE[k] + g_attnh[k] - m);
                s_w[k] = e;
                ssum += e;
            }
            ssum = wredu(ssum);
            if (lane == 0) s_S = ssum;
        }
        __syncthreads();
        {
            const float invS = 1.f / s_S;
            const float* cE = g_combE + tok * H;
            for (int i = WGID; i < H; i += NW) {
                const float* Mr = g_M + i * MPAD;
                float s = 0.f;
                for (int k = lane; k < AROWS; k += 32) s = fmaf(s_w[k], Mr[k], s);
                s = wredu(s);
                if (lane == 0) g_x[i] = fmaxf(0.f, cE[i] + s * invS);
            }
        }
        grid_sync();

        // --- P3: gi = dec_Wih @ x, gates -> h' ---
        {
            const float* hold = h;
            float* hnew = g_h[cur ^ 1];
            for (int j = WGID; j < H; j += NW) {
                float gi[3];
                dot3h(g_dWih_h + (size_t)j * H, g_dWih_h + (size_t)(H + j) * H,
                      g_dWih_h + (size_t)(2 * H + j) * H, g_x, lane, gi);
                float ar = wredu(gi[0]);
                float az = wredu(gi[1]);
                float an = wredu(gi[2]);
                if (lane == 0) {
                    float r = sigm(ar + dec_bih[j]          + g_gh[j]);
                    float z = sigm(az + dec_bih[H + j]      + g_gh[H + j]);
                    float n = tanhf(an + dec_bih[2 * H + j] + r * g_gh[2 * H + j]);
                    hnew[j] = (1.f - z) * n + z * hold[j];
                }
            }
        }
        grid_sync();
        cur ^= 1;
    }

    // ---- final logits for row ML-1 ----
    {
        const float* hf = g_h[cur];
        for (int v = WGID; v < HV; v += NW) {
            float s = wredu(dot1536h(g_outW_h + v * H, hf, lane));
            if (lane == 0) g_o[v] = s + out_b[v];
        }
    }
    grid_sync();

    if (blockIdx.x == 0 && wid == 0) {
        float m = -1e30f; int am = HV;
        for (int v = lane; v < HV; v += 32) {
            float ov = g_o[v];
            if (ov > m) { m = ov; am = v; }
        }
        wargmax(m, am);
        float e = 0.f;
        for (int v = lane; v < HV; v += 32) e += expf(g_o[v] - m);
        e = wredu(e);
        float lse = m + logf(e);
        for (int v = lane; v < HV; v += 32) out[(ML - 1) * HV + v] = g_o[v] - lse;
        if (lane == 0 && write_tok) out[ML * HV + (ML - 1)] = (float)am;
    }
}

// ---------------- launch ----------------
extern "C" void kernel_launch(void* const* d_in, const int* in_sizes, int n_in,
                              void* d_out, int out_size) {
    const int*   input   = (const int*)  d_in[0];
    const int    L       = in_sizes[0];
    // d_in[1] = max_length scalar (compile-time ML=128)
    const float* emb_enc = (const float*)d_in[2];
    const float* enc_Wih = (const float*)d_in[3];
    const float* enc_Whh = (const float*)d_in[4];
    const float* enc_bih = (const float*)d_in[5];
    const float* enc_bhh = (const float*)d_in[6];
    const float* emb_dec = (const float*)d_in[7];
    const float* attn_W  = (const float*)d_in[8];
    const float* attn_b  = (const float*)d_in[9];
    const float* comb_W  = (const float*)d_in[10];
    const float* comb_b  = (const float*)d_in[11];
    const float* dec_Wih = (const float*)d_in[12];
    const float* dec_Whh = (const float*)d_in[13];
    const float* dec_bih = (const float*)d_in[14];
    const float* dec_bhh = (const float*)d_in[15];
    const float* out_W   = (const float*)d_in[16];
    const float* out_b   = (const float*)d_in[17];

    int write_tok = (out_size >= ML * HV + ML) ? 1 : 0;

    const int nBig = H3 * H / 4;    // float4s per big matrix
    cvt_kernel<<<592, 256>>>((const float4*)enc_Wih, nBig, 0);
    cvt_kernel<<<592, 256>>>((const float4*)enc_Whh, nBig, 1);
    cvt_kernel<<<592, 256>>>((const float4*)dec_Wih, nBig, 2);
    cvt_kernel<<<592, 256>>>((const float4*)dec_Whh, nBig, 3);
    cvt_kernel<<<148, 256>>>((const float4*)out_W, HV * H / 4, 4);
    cvt_attn_kernel<<<148, 256>>>(attn_W);

    seq2seq_kernel<<<GRID, BLOCK>>>(input, L, emb_enc,
                                    enc_bih, enc_bhh,
                                    emb_dec, attn_W, attn_b, comb_W, comb_b,
                                    dec_bih, dec_bhh,
                                    out_b,
                                    (float*)d_out, write_tok);
}

// round 12
// speedup vs baseline: 1.4127x; 1.0416x over previous
#include <cuda_runtime.h>
#include <cuda_fp16.h>
#include <math.h>

// Problem constants
#define H     1536
#define H3    4608          // 3*H
#define HV    128           // vocab
#define ML    128           // max_length
#define AROWS 129           // ML+1 attention rows
#define MPAD  132           // padded row stride for 129-wide matrices
#define GRID  148
#define BLOCK 1024

// ---------------- device scratch (no allocations allowed) ----------------
__device__ __align__(16) float g_h[2][H];             // ping-pong hidden state
__device__ __align__(16) float g_encout[AROWS * H];   // encoder_outputs (129 x 1536)
__device__ __align__(16) float g_gh[H3];              // dec_Whh @ h + bhh
__device__ __align__(16) float g_attnh[AROWS];        // attn h-half logits
__device__ __align__(16) float g_o[HV];               // output logits
__device__ __align__(16) float g_x[H];                // relu(comb) input to dec GRU
__device__ __align__(16) float g_M[H * MPAD];         // comb_W_ctx @ encout^T  (1536 x 129)
__device__ __align__(16) float g_attE[HV * MPAD];     // attn_W_emb @ emb_dec^T + attn_b
__device__ __align__(16) float g_combE[HV * H];       // comb_W_emb @ emb_dec^T + comb_b
__device__ unsigned g_bar;                            // grid barrier (monotonic)

// fp16 weight copies (converted by pre-kernels each replay; deterministic)
__device__ __align__(16) __half g_eWih_h[(size_t)H3 * H];
__device__ __align__(16) __half g_eWhh_h[(size_t)H3 * H];
__device__ __align__(16) __half g_dWih_h[(size_t)H3 * H];
__device__ __align__(16) __half g_dWhh_h[(size_t)H3 * H];
__device__ __align__(16) __half g_outW_h[HV * H];
__device__ __align__(16) __half g_attnWh_h[AROWS * H];   // attn_W h-half

// ---------------- conversion pre-kernels ----------------
__global__ void cvt_kernel(const float4* __restrict__ src, int n4, int which) {
    __half2* dst;
    switch (which) {
        case 0: dst = (__half2*)g_eWih_h; break;
        case 1: dst = (__half2*)g_eWhh_h; break;
        case 2: dst = (__half2*)g_dWih_h; break;
        case 3: dst = (__half2*)g_dWhh_h; break;
        default: dst = (__half2*)g_outW_h; break;
    }
    int i  = blockIdx.x * blockDim.x + threadIdx.x;
    int st = gridDim.x * blockDim.x;
    for (; i < n4; i += st) {
        float4 v = src[i];
        dst[2 * i]     = __floats2half2_rn(v.x, v.y);
        dst[2 * i + 1] = __floats2half2_rn(v.z, v.w);
    }
}

// attn_W h-half (row stride 2H, offset H)
__global__ void cvt_attn_kernel(const float* __restrict__ attn_W) {
    int i  = blockIdx.x * blockDim.x + threadIdx.x;
    int st = gridDim.x * blockDim.x;
    int n4 = AROWS * H / 4;
    __half2* dst = (__half2*)g_attnWh_h;
    for (; i < n4; i += st) {
        int k = (i * 4) / H, c = (i * 4) % H;
        const float4 v = *(const float4*)(attn_W + k * (2 * H) + H + c);
        dst[2 * i]     = __floats2half2_rn(v.x, v.y);
        dst[2 * i + 1] = __floats2half2_rn(v.z, v.w);
    }
}

// ---------------- grid-wide barrier (all 148 CTAs resident: 1 CTA/SM) ----
__device__ __forceinline__ void grid_sync() {
    __syncthreads();
    if (threadIdx.x == 0) {
        __threadfence();
        unsigned nb  = gridDim.x;
        unsigned old = atomicAdd(&g_bar, 1u);
        unsigned target = old - (old % nb) + nb;   // next multiple of nb
        while ((int)(*(volatile unsigned*)&g_bar - target) < 0) { }
        __threadfence();
    }
    __syncthreads();
}

// ---------------- warp helpers ----------------
__device__ __forceinline__ float wredu(float v) {
#pragma unroll
    for (int o = 16; o; o >>= 1) v += __shfl_xor_sync(0xffffffffu, v, o);
    return v;
}

// argmax with first-index tie-break (matches jnp.argmax)
__device__ __forceinline__ void wargmax(float& m, int& am) {
#pragma unroll
    for (int o = 16; o; o >>= 1) {
        float m2 = __shfl_xor_sync(0xffffffffu, m, o);
        int   a2 = __shfl_xor_sync(0xffffffffu, am, o);
        if (m2 > m || (m2 == m && a2 < am)) { m = m2; am = a2; }
    }
}

__device__ __forceinline__ float sigm(float x) { return 1.f / (1.f + expf(-x)); }

// 8 fp16 weights (one uint4) against 8 fp32 vector elems; register-safe casts
__device__ __forceinline__ float acc8(uint4 A, float4 b0, float4 b1, float s) {
    __half2 h0 = *reinterpret_cast<const __half2*>(&A.x);
    __half2 h1 = *reinterpret_cast<const __half2*>(&A.y);
    __half2 h2 = *reinterpret_cast<const __half2*>(&A.z);
    __half2 h3 = *reinterpret_cast<const __half2*>(&A.w);
    float2 f;
    f = __half22float2(h0); s = fmaf(f.x, b0.x, s); s = fmaf(f.y, b0.y, s);
    f = __half22float2(h1); s = fmaf(f.x, b0.z, s); s = fmaf(f.y, b0.w, s);
    f = __half22float2(h2); s = fmaf(f.x, b1.x, s); s = fmaf(f.y, b1.y, s);
    f = __half22float2(h3); s = fmaf(f.x, b1.z, s); s = fmaf(f.y, b1.w, s);
    return s;
}

// fp16 weight row . fp32 vector
__device__ __forceinline__ float dot1536h(const __half* __restrict__ w,
                                          const float* __restrict__ x, int lane) {
    const uint4*  w8 = (const uint4*)w;
    const float4* x4 = (const float4*)x;
    float s = 0.f;
#pragma unroll
    for (int i = 0; i < 6; i++) {
        int idx = lane + 32 * i;
        s = acc8(w8[idx], x4[2 * idx], x4[2 * idx + 1], s);
    }
    return s;
}

// three fp16 rows vs one fp32 vector (shared vector loads)
__device__ __forceinline__ void dot3h(const __half* __restrict__ w0,
                                      const __half* __restrict__ w1,
                                      const __half* __restrict__ w2,
                                      const float* __restrict__ x,
                                      int lane, float* r) {
    const uint4*  a0 = (const uint4*)w0;
    const uint4*  a1 = (const uint4*)w1;
    const uint4*  a2 = (const uint4*)w2;
    const float4* x4 = (const float4*)x;
    float s0 = 0.f, s1 = 0.f, s2 = 0.f;
#pragma unroll
    for (int i = 0; i < 6; i++) {
        int idx = lane + 32 * i;
        float4 b0 = x4[2 * idx];
        float4 b1 = x4[2 * idx + 1];
        s0 = acc8(a0[idx], b0, b1, s0);
        s1 = acc8(a1[idx], b0, b1, s1);
        s2 = acc8(a2[idx], b0, b1, s2);
    }
    r[0] = s0; r[1] = s1; r[2] = s2;
}

// fp32: 4 dots sharing one weight row (R5's untiled precompute GEMMs)
__device__ __forceinline__ void dot1536x4(const float* __restrict__ w,
                                          const float* __restrict__ x0,
                                          const float* __restrict__ x1,
                                          const float* __restrict__ x2,
                                          const float* __restrict__ x3,
                                          int lane, float* r) {
    const float4* w4 = (const float4*)w;
    const float4* a0 = (const float4*)x0;
    const float4* a1 = (const float4*)x1;
    const float4* a2 = (const float4*)x2;
    const float4* a3 = (const float4*)x3;
    float s0 = 0.f, s1 = 0.f, s2 = 0.f, s3 = 0.f;
#pragma unroll 4
    for (int i = 0; i < 12; i++) {
        float4 a = w4[lane + 32 * i];
        float4 b;
        b = a0[lane + 32 * i];
        s0 = fmaf(a.x, b.x, s0); s0 = fmaf(a.y, b.y, s0);
        s0 = fmaf(a.z, b.z, s0); s0 = fmaf(a.w, b.w, s0);
        b = a1[lane + 32 * i];
        s1 = fmaf(a.x, b.x, s1); s1 = fmaf(a.y, b.y, s1);
        s1 = fmaf(a.z, b.z, s1); s1 = fmaf(a.w, b.w, s1);
        b = a2[lane + 32 * i];
        s2 = fmaf(a.x, b.x, s2); s2 = fmaf(a.y, b.y, s2);
        s2 = fmaf(a.z, b.z, s2); s2 = fmaf(a.w, b.w, s2);
        b = a3[lane + 32 * i];
        s3 = fmaf(a.x, b.x, s3); s3 = fmaf(a.y, b.y, s3);
        s3 = fmaf(a.z, b.z, s3); s3 = fmaf(a.w, b.w, s3);
    }
    r[0] = s0; r[1] = s1; r[2] = s2; r[3] = s3;
}

// ---------------- persistent kernel ----------------
__global__ __launch_bounds__(BLOCK, 1)
void seq2seq_kernel(const int* __restrict__ input, int L,
                    const float* __restrict__ emb_enc,
                    const float* __restrict__ enc_bih, const float* __restrict__ enc_bhh,
                    const float* __restrict__ emb_dec,
                    const float* __restrict__ attn_W, const float* __restrict__ attn_b,
                    const float* __restrict__ comb_W, const float* __restrict__ comb_b,
                    const float* __restrict__ dec_bih, const float* __restrict__ dec_bhh,
                    const float* __restrict__ out_b,
                    float* __restrict__ out, int write_tok)
{
    const int tid  = threadIdx.x;
    const int lane = tid & 31;
    const int wid  = tid >> 5;
    // interleave warp ids across blocks so every phase keeps all SMs busy
    const int WGID = wid * gridDim.x + blockIdx.x;
    const int NW   = gridDim.x * (blockDim.x >> 5);

    __shared__ float s_w[AROWS];     // unnormalized softmax weights
    __shared__ float s_S, s_lse;
    __shared__ int   s_tok;

    // ---- init: zero h0 and the unused tail rows of encoder_outputs ----
    {
        int gt = blockIdx.x * blockDim.x + tid;
        int NT = gridDim.x * blockDim.x;
        for (int i = gt; i < H; i += NT) g_h[0][i] = 0.f;
        for (int i = L * H + gt; i < AROWS * H; i += NT) g_encout[i] = 0.f;
    }

    // ---- P_E (R5 untiled): emb-half GEMMs for attn and comb + bias fold ----
    // virtual rows: [0,AROWS) -> attn_W emb-half, [AROWS,AROWS+H) -> comb_W emb-half
    {
        int b  = blockIdx.x;
        int r0 = b * 11 + min(b, 37);
        int nr = 11 + (b < 37 ? 1 : 0);       // 37*12 + 111*11 = 1665 rows
        for (int u = wid; u < nr * 32; u += 32) {
            int lr = u >> 5;
            int vc = (u & 31) << 2;           // vocab chunk base (0..124)
            int r  = r0 + lr;
            const float* w; float bias;
            if (r < AROWS) { w = attn_W + r * (2 * H); bias = attn_b[r]; }
            else           { w = comb_W + (r - AROWS) * (2 * H); bias = comb_b[r - AROWS]; }
            float s[4];
            dot1536x4(w, emb_dec + vc * H, emb_dec + (vc + 1) * H,
                         emb_dec + (vc + 2) * H, emb_dec + (vc + 3) * H, lane, s);
#pragma unroll
            for (int q = 0; q < 4; q++) s[q] = wredu(s[q]);
            if (lane == 0) {
#pragma unroll
                for (int q = 0; q < 4; q++) {
                    if (r < AROWS) g_attE[(vc + q) * MPAD + r] = s[q] + bias;
                    else           g_combE[(vc + q) * H + (r - AROWS)] = s[q] + bias;
                }
            }
        }
    }
    grid_sync();

    int cur = 0;

    // =========================== ENCODER ===========================
    for (int t = 0; t < L; t++) {
        const float* x    = emb_enc + __ldg(&input[t]) * H;
        const float* hold = g_h[cur];
        float*       hnew = g_h[cur ^ 1];

        for (int j = WGID; j < H; j += NW) {
            float gi[3], gh3[3];
            dot3h(g_eWih_h + (size_t)j * H, g_eWih_h + (size_t)(H + j) * H,
                  g_eWih_h + (size_t)(2 * H + j) * H, x, lane, gi);
            dot3h(g_eWhh_h + (size_t)j * H, g_eWhh_h + (size_t)(H + j) * H,
                  g_eWhh_h + (size_t)(2 * H + j) * H, hold, lane, gh3);
            float rp  = wredu(gi[0] + gh3[0]);
            float zp  = wredu(gi[1] + gh3[1]);
            float anr = wredu(gi[2]);
            float bnr = wredu(gh3[2]);
            if (lane == 0) {
                float r  = sigm(rp + enc_bih[j] + enc_bhh[j]);
                float z  = sigm(zp + enc_bih[H + j] + enc_bhh[H + j]);
                float n  = tanhf(anr + enc_bih[2 * H + j] + r * (bnr + enc_bhh[2 * H + j]));
                float hv = (1.f - z) * n + z * hold[j];
                hnew[j] = hv;
                g_encout[t * H + j] = hv;
            }
        }
        grid_sync();
        cur ^= 1;
    }

    // ---- P_M (R5 untiled): M[i][k] = comb_W_ctx[i,:] . encout[k,:] ----
    {
        int b  = blockIdx.x;
        int r0 = b * 10 + min(b, 56);
        int nr = 10 + (b < 56 ? 1 : 0);       // 56*11 + 92*10 = 1536 rows
        for (int u = wid; u < nr * 33; u += 32) {
            int lr = u / 33;
            int kc = (u % 33) * 4;            // 0..128
            int i  = r0 + lr;
            const float* w = comb_W + i * (2 * H) + H;
            int k0 = min(kc,     AROWS - 1);
            int k1 = min(kc + 1, AROWS - 1);
            int k2 = min(kc + 2, AROWS - 1);
            int k3 = min(kc + 3, AROWS - 1);
            float s[4];
            dot1536x4(w, g_encout + k0 * H, g_encout + k1 * H,
                         g_encout + k2 * H, g_encout + k3 * H, lane, s);
#pragma unroll
            for (int q = 0; q < 4; q++) s[q] = wredu(s[q]);
            if (lane == 0) {
#pragma unroll
                for (int q = 0; q < 4; q++) {
                    int k = kc + q;
                    if (k < AROWS) g_M[i * MPAD + k] = s[q];
                }
            }
        }
    }
    grid_sync();

    // =========================== DECODER ===========================
    for (int t = 0; t < ML; t++) {
        const float* h = g_h[cur];

        // --- P1: gh = Whh.h+bhh (4608) || out logits (128) || attn_h (129) ---
        for (int task = WGID; task < H3 + HV + AROWS; task += NW) {
            if (task < H3) {
                float s = wredu(dot1536h(g_dWhh_h + (size_t)task * H, h, lane));
                if (lane == 0) g_gh[task] = s + dec_bhh[task];
            } else if (task < H3 + HV) {
                int v = task - H3;
                float s = wredu(dot1536h(g_outW_h + v * H, h, lane));
                if (lane == 0) g_o[v] = s + out_b[v];
            } else {
                int k = task - H3 - HV;
                float s = wredu(dot1536h(g_attnWh_h + k * H, h, lane));
                if (lane == 0) g_attnh[k] = s;
            }
        }
        grid_sync();

        // --- P2: token select, emit row t-1, softmax, x rows ---
        if (wid == 0) {
            int tok; float lse;
            if (t == 0) { tok = 0; lse = 0.f; }
            else {
                float m = -1e30f; int am = HV;
                for (int v = lane; v < HV; v += 32) {
                    float ov = g_o[v];
                    if (ov > m) { m = ov; am = v; }
                }
                wargmax(m, am);
                float e = 0.f;
                for (int v = lane; v < HV; v += 32) e += expf(g_o[v] - m);
                e = wredu(e);
                lse = m + logf(e);
                tok = am;
            }
            if (lane == 0) { s_tok = tok; s_lse = lse; }
        }
        __syncthreads();
        const int tok = s_tok;
        if (t > 0 && blockIdx.x == 0 && wid == 1) {
            for (int v = lane; v < HV; v += 32) out[(t - 1) * HV + v] = g_o[v] - s_lse;
            if (lane == 0 && write_tok) out[ML * HV + (t - 1)] = (float)tok;
        }
        if (wid == 0) {
            const float* aE = g_attE + tok * MPAD;
            float m = -1e30f;
            for (int k = lane; k < AROWS; k += 32) m = fmaxf(m, aE[k] + g_attnh[k]);
#pragma unroll
            for (int o = 16; o; o >>= 1) m = fmaxf(m, __shfl_xor_sync(0xffffffffu, m, o));
            float ssum = 0.f;
            for (int k = lane; k < AROWS; k += 32) {
                float e = expf(aE[k] + g_attnh[k] - m);
                s_w[k] = e;
                ssum += e;
            }
            ssum = wredu(ssum);
            if (lane == 0) s_S = ssum;
        }
        __syncthreads();
        {
            const float invS = 1.f / s_S;
            const float* cE = g_combE + tok * H;
            for (int i = WGID; i < H; i += NW) {
                const float* Mr = g_M + i * MPAD;
                float s = 0.f;
                for (int k = lane; k < AROWS; k += 32) s = fmaf(s_w[k], Mr[k], s);
                s = wredu(s);
                if (lane == 0) g_x[i] = fmaxf(0.f, cE[i] + s * invS);
            }
        }
        grid_sync();

        // --- P3: gi = dec_Wih @ x, gates -> h' ---
        {
            const float* hold = h;
            float* hnew = g_h[cur ^ 1];
            for (int j = WGID; j < H; j += NW) {
                float gi[3];
                dot3h(g_dWih_h + (size_t)j * H, g_dWih_h + (size_t)(H + j) * H,
                      g_dWih_h + (size_t)(2 * H + j) * H, g_x, lane, gi);
                float ar = wredu(gi[0]);
                float az = wredu(gi[1]);
                float an = wredu(gi[2]);
                if (lane == 0) {
                    float r = sigm(ar + dec_bih[j]          + g_gh[j]);
                    float z = sigm(az + dec_bih[H + j]      + g_gh[H + j]);
                    float n = tanhf(an + dec_bih[2 * H + j] + r * g_gh[2 * H + j]);
                    hnew[j] = (1.f - z) * n + z * hold[j];
                }
            }
        }
        grid_sync();
        cur ^= 1;
    }

    // ---- final logits for row ML-1 ----
    {
        const float* hf = g_h[cur];
        for (int v = WGID; v < HV; v += NW) {
            float s = wredu(dot1536h(g_outW_h + v * H, hf, lane));
            if (lane == 0) g_o[v] = s + out_b[v];
        }
    }
    grid_sync();

    if (blockIdx.x == 0 && wid == 0) {
        float m = -1e30f; int am = HV;
        for (int v = lane; v < HV; v += 32) {
            float ov = g_o[v];
            if (ov > m) { m = ov; am = v; }
        }
        wargmax(m, am);
        float e = 0.f;
        for (int v = lane; v < HV; v += 32) e += expf(g_o[v] - m);
        e = wredu(e);
        float lse = m + logf(e);
        for (int v = lane; v < HV; v += 32) out[(ML - 1) * HV + v] = g_o[v] - lse;
        if (lane == 0 && write_tok) out[ML * HV + (ML - 1)] = (float)am;
    }
}

// ---------------- launch ----------------
extern "C" void kernel_launch(void* const* d_in, const int* in_sizes, int n_in,
                              void* d_out, int out_size) {
    const int*   input   = (const int*)  d_in[0];
    const int    L       = in_sizes[0];
    // d_in[1] = max_length scalar (compile-time ML=128)
    const float* emb_enc = (const float*)d_in[2];
    const float* enc_Wih = (const float*)d_in[3];
    const float* enc_Whh = (const float*)d_in[4];
    const float* enc_bih = (const float*)d_in[5];
    const float* enc_bhh = (const float*)d_in[6];
    const float* emb_dec = (const float*)d_in[7];
    const float* attn_W  = (const float*)d_in[8];
    const float* attn_b  = (const float*)d_in[9];
    const float* comb_W  = (const float*)d_in[10];
    const float* comb_b  = (const float*)d_in[11];
    const float* dec_Wih = (const float*)d_in[12];
    const float* dec_Whh = (const float*)d_in[13];
    const float* dec_bih = (const float*)d_in[14];
    const float* dec_bhh = (const float*)d_in[15];
    const float* out_W   = (const float*)d_in[16];
    const float* out_b   = (const float*)d_in[17];

    int write_tok = (out_size >= ML * HV + ML) ? 1 : 0;

    const int nBig = H3 * H / 4;    // float4s per big matrix
    cvt_kernel<<<592, 256>>>((const float4*)enc_Wih, nBig, 0);
    cvt_kernel<<<592, 256>>>((const float4*)enc_Whh, nBig, 1);
    cvt_kernel<<<592, 256>>>((const float4*)dec_Wih, nBig, 2);
    cvt_kernel<<<592, 256>>>((const float4*)dec_Whh, nBig, 3);
    cvt_kernel<<<148, 256>>>((const float4*)out_W, HV * H / 4, 4);
    cvt_attn_kernel<<<148, 256>>>(attn_W);

    seq2seq_kernel<<<GRID, BLOCK>>>(input, L, emb_enc,
                                    enc_bih, enc_bhh,
                                    emb_dec, attn_W, attn_b, comb_W, comb_b,
                                    dec_bih, dec_bhh,
                                    out_b,
                                    (float*)d_out, write_tok);
}

// round 13
// speedup vs baseline: 1.4556x; 1.0304x over previous
#include <cuda_runtime.h>
#include <cuda_fp16.h>
#include <math.h>

// Problem constants
#define H     1536
#define H3    4608          // 3*H
#define HV    128           // vocab
#define ML    128           // max_length
#define AROWS 129           // ML+1 attention rows
#define MPAD  132           // padded row stride for 129-wide matrices
#define GRID  148
#define BLOCK 1024

// ---------------- device scratch (no allocations allowed) ----------------
__device__ __align__(16) float g_h[2][H];             // ping-pong hidden state
__device__ __align__(16) float g_encout[AROWS * H];   // encoder_outputs (129 x 1536)
__device__ __align__(16) float g_gh[H3];              // dec_Whh @ h + bhh
__device__ __align__(16) float g_attnh[AROWS];        // attn h-half logits
__device__ __align__(16) float g_o[HV];               // output logits
__device__ __align__(16) float g_x[H];                // relu(comb) input to dec GRU
__device__ __align__(16) float g_M[H * MPAD];         // comb_W_ctx @ encout^T  (write-once)
__device__ __align__(16) float g_attE[HV * MPAD];     // attn_W_emb @ emb_dec^T + attn_b (write-once)
__device__ __align__(16) float g_combE[HV * H];       // comb_W_emb @ emb_dec^T + comb_b (write-once)
__device__ unsigned g_bar;                            // grid barrier (monotonic)

// fp16 weight copies (converted by pre-kernels each replay; deterministic)
__device__ __align__(16) __half g_eWih_h[(size_t)H3 * H];
__device__ __align__(16) __half g_eWhh_h[(size_t)H3 * H];
__device__ __align__(16) __half g_dWih_h[(size_t)H3 * H];
__device__ __align__(16) __half g_dWhh_h[(size_t)H3 * H];
__device__ __align__(16) __half g_outW_h[HV * H];
__device__ __align__(16) __half g_attnWh_h[AROWS * H];   // attn_W h-half

// ---------------- conversion pre-kernels ----------------
__global__ void cvt_kernel(const float4* __restrict__ src, int n4, int which) {
    __half2* dst;
    switch (which) {
        case 0: dst = (__half2*)g_eWih_h; break;
        case 1: dst = (__half2*)g_eWhh_h; break;
        case 2: dst = (__half2*)g_dWih_h; break;
        case 3: dst = (__half2*)g_dWhh_h; break;
        default: dst = (__half2*)g_outW_h; break;
    }
    int i  = blockIdx.x * blockDim.x + threadIdx.x;
    int st = gridDim.x * blockDim.x;
    for (; i < n4; i += st) {
        float4 v = src[i];
        dst[2 * i]     = __floats2half2_rn(v.x, v.y);
        dst[2 * i + 1] = __floats2half2_rn(v.z, v.w);
    }
}

// attn_W h-half (row stride 2H, offset H)
__global__ void cvt_attn_kernel(const float* __restrict__ attn_W) {
    int i  = blockIdx.x * blockDim.x + threadIdx.x;
    int st = gridDim.x * blockDim.x;
    int n4 = AROWS * H / 4;
    __half2* dst = (__half2*)g_attnWh_h;
    for (; i < n4; i += st) {
        int k = (i * 4) / H, c = (i * 4) % H;
        const float4 v = *(const float4*)(attn_W + k * (2 * H) + H + c);
        dst[2 * i]     = __floats2half2_rn(v.x, v.y);
        dst[2 * i + 1] = __floats2half2_rn(v.z, v.w);
    }
}

// ---- grid barrier: release-add / acquire-poll (no CCTL.IVALL L1 flush) ----
// Sound because every mutable cross-phase global READ uses __ldcg (L2-direct);
// write-once tables are only ever cold-read per SM, so .ca copies never go stale.
__device__ __forceinline__ void grid_sync() {
    __syncthreads();
    if (threadIdx.x == 0) {
        unsigned* p = &g_bar;
        unsigned old;
        asm volatile("atom.release.gpu.global.add.u32 %0, [%1], %2;"
                     : "=r"(old) : "l"(p), "r"(1u) : "memory");
        unsigned target = old - (old % GRID) + GRID;
        unsigned v;
        for (;;) {
            asm volatile("ld.acquire.gpu.global.u32 %0, [%1];"
                         : "=r"(v) : "l"(p) : "memory");
            if ((int)(v - target) >= 0) break;
            __nanosleep(32);
        }
    }
    __syncthreads();
}

// ---------------- warp helpers ----------------
__device__ __forceinline__ float wredu(float v) {
#pragma unroll
    for (int o = 16; o; o >>= 1) v += __shfl_xor_sync(0xffffffffu, v, o);
    return v;
}

// argmax with first-index tie-break (matches jnp.argmax)
__device__ __forceinline__ void wargmax(float& m, int& am) {
#pragma unroll
    for (int o = 16; o; o >>= 1) {
        float m2 = __shfl_xor_sync(0xffffffffu, m, o);
        int   a2 = __shfl_xor_sync(0xffffffffu, am, o);
        if (m2 > m || (m2 == m && a2 < am)) { m = m2; am = a2; }
    }
}

__device__ __forceinline__ float sigm(float x) { return 1.f / (1.f + expf(-x)); }

// 8 fp16 weights (one uint4) against 8 fp32 vector elems; register-safe casts
__device__ __forceinline__ float acc8(uint4 A, float4 b0, float4 b1, float s) {
    __half2 h0 = *reinterpret_cast<const __half2*>(&A.x);
    __half2 h1 = *reinterpret_cast<const __half2*>(&A.y);
    __half2 h2 = *reinterpret_cast<const __half2*>(&A.z);
    __half2 h3 = *reinterpret_cast<const __half2*>(&A.w);
    float2 f;
    f = __half22float2(h0); s = fmaf(f.x, b0.x, s); s = fmaf(f.y, b0.y, s);
    f = __half22float2(h1); s = fmaf(f.x, b0.z, s); s = fmaf(f.y, b0.w, s);
    f = __half22float2(h2); s = fmaf(f.x, b1.x, s); s = fmaf(f.y, b1.y, s);
    f = __half22float2(h3); s = fmaf(f.x, b1.z, s); s = fmaf(f.y, b1.w, s);
    return s;
}

// fp16 weight row (global) . fp32 vector (SMEM-staged)
__device__ __forceinline__ float dot1536h(const __half* __restrict__ w,
                                          const float4* __restrict__ sx, int lane) {
    const uint4* w8 = (const uint4*)w;
    float s = 0.f;
#pragma unroll
    for (int i = 0; i < 6; i++) {
        int idx = lane + 32 * i;
        s = acc8(w8[idx], sx[2 * idx], sx[2 * idx + 1], s);
    }
    return s;
}

// three fp16 rows vs one SMEM-staged fp32 vector (shared vector loads)
__device__ __forceinline__ void dot3h(const __half* __restrict__ w0,
                                      const __half* __restrict__ w1,
                                      const __half* __restrict__ w2,
                                      const float4* __restrict__ sx,
                                      int lane, float* r) {
    const uint4* a0 = (const uint4*)w0;
    const uint4* a1 = (const uint4*)w1;
    const uint4* a2 = (const uint4*)w2;
    float s0 = 0.f, s1 = 0.f, s2 = 0.f;
#pragma unroll
    for (int i = 0; i < 6; i++) {
        int idx = lane + 32 * i;
        float4 b0 = sx[2 * idx];
        float4 b1 = sx[2 * idx + 1];
        s0 = acc8(a0[idx], b0, b1, s0);
        s1 = acc8(a1[idx], b0, b1, s1);
        s2 = acc8(a2[idx], b0, b1, s2);
    }
    r[0] = s0; r[1] = s1; r[2] = s2;
}

// fp32: 4 dots sharing one weight row (untiled precompute GEMMs)
__device__ __forceinline__ void dot1536x4(const float* __restrict__ w,
                                          const float* __restrict__ x0,
                                          const float* __restrict__ x1,
                                          const float* __restrict__ x2,
                                          const float* __restrict__ x3,
                                          int lane, float* r) {
    const float4* w4 = (const float4*)w;
    const float4* a0 = (const float4*)x0;
    const float4* a1 = (const float4*)x1;
    const float4* a2 = (const float4*)x2;
    const float4* a3 = (const float4*)x3;
    float s0 = 0.f, s1 = 0.f, s2 = 0.f, s3 = 0.f;
#pragma unroll 4
    for (int i = 0; i < 12; i++) {
        float4 a = w4[lane + 32 * i];
        float4 b;
        b = a0[lane + 32 * i];
        s0 = fmaf(a.x, b.x, s0); s0 = fmaf(a.y, b.y, s0);
        s0 = fmaf(a.z, b.z, s0); s0 = fmaf(a.w, b.w, s0);
        b = a1[lane + 32 * i];
        s1 = fmaf(a.x, b.x, s1); s1 = fmaf(a.y, b.y, s1);
        s1 = fmaf(a.z, b.z, s1); s1 = fmaf(a.w, b.w, s1);
        b = a2[lane + 32 * i];
        s2 = fmaf(a.x, b.x, s2); s2 = fmaf(a.y, b.y, s2);
        s2 = fmaf(a.z, b.z, s2); s2 = fmaf(a.w, b.w, s2);
        b = a3[lane + 32 * i];
        s3 = fmaf(a.x, b.x, s3); s3 = fmaf(a.y, b.y, s3);
        s3 = fmaf(a.z, b.z, s3); s3 = fmaf(a.w, b.w, s3);
    }
    r[0] = s0; r[1] = s1; r[2] = s2; r[3] = s3;
}

// ---------------- persistent kernel ----------------
__global__ __launch_bounds__(BLOCK, 1)
void seq2seq_kernel(const int* __restrict__ input, int L,
                    const float* __restrict__ emb_enc,
                    const float* __restrict__ enc_bih, const float* __restrict__ enc_bhh,
                    const float* __restrict__ emb_dec,
                    const float* __restrict__ attn_W, const float* __restrict__ attn_b,
                    const float* __restrict__ comb_W, const float* __restrict__ comb_b,
                    const float* __restrict__ dec_bih, const float* __restrict__ dec_bhh,
                    const float* __restrict__ out_b,
                    float* __restrict__ out, int write_tok)
{
    const int tid  = threadIdx.x;
    const int lane = tid & 31;
    const int wid  = tid >> 5;
    const int WGID = wid * GRID + blockIdx.x;
    const int NW   = GRID * (BLOCK >> 5);

    __shared__ __align__(16) float s_h[H];   // staged hidden state
    __shared__ __align__(16) float s_x[H];   // staged emb / x vector
    __shared__ float s_w[AROWS];             // unnormalized softmax weights
    __shared__ float s_S, s_lse;
    __shared__ int   s_tok;
    float4* s_h4 = (float4*)s_h;
    float4* s_x4 = (float4*)s_x;

    // ---- init: zero h0 and the unused tail rows of encoder_outputs ----
    {
        int gt = blockIdx.x * BLOCK + tid;
        int NT = GRID * BLOCK;
        for (int i = gt; i < H; i += NT) g_h[0][i] = 0.f;
        for (int i = L * H + gt; i < AROWS * H; i += NT) g_encout[i] = 0.f;
    }

    // ---- P_E (untiled): emb-half GEMMs for attn and comb + bias fold ----
    {
        int b  = blockIdx.x;
        int r0 = b * 11 + min(b, 37);
        int nr = 11 + (b < 37 ? 1 : 0);       // 37*12 + 111*11 = 1665 rows
        for (int u = wid; u < nr * 32; u += 32) {
            int lr = u >> 5;
            int vc = (u & 31) << 2;           // vocab chunk base (0..124)
            int r  = r0 + lr;
            const float* w; float bias;
            if (r < AROWS) { w = attn_W + r * (2 * H); bias = attn_b[r]; }
            else           { w = comb_W + (r - AROWS) * (2 * H); bias = comb_b[r - AROWS]; }
            float s[4];
            dot1536x4(w, emb_dec + vc * H, emb_dec + (vc + 1) * H,
                         emb_dec + (vc + 2) * H, emb_dec + (vc + 3) * H, lane, s);
#pragma unroll
            for (int q = 0; q < 4; q++) s[q] = wredu(s[q]);
            if (lane == 0) {
#pragma unroll
                for (int q = 0; q < 4; q++) {
                    if (r < AROWS) g_attE[(vc + q) * MPAD + r] = s[q] + bias;
                    else           g_combE[(vc + q) * H + (r - AROWS)] = s[q] + bias;
                }
            }
        }
    }
    grid_sync();

    int cur = 0;

    // =========================== ENCODER ===========================
    for (int t = 0; t < L; t++) {
        // stage emb row and current hidden state into SMEM
        {
            int tk = __ldg(&input[t]);
            const float4* e4 = (const float4*)(emb_enc + tk * H);
            const float4* h4 = (const float4*)g_h[cur];
            if (tid < 384)                  s_x4[tid]       = __ldg(e4 + tid);
            else if (tid < 768)             s_h4[tid - 384] = __ldcg(h4 + (tid - 384));
            __syncthreads();
        }
        float* hnew = g_h[cur ^ 1];

        for (int j = WGID; j < H; j += NW) {
            float gi[3], gh3[3];
            dot3h(g_eWih_h + (size_t)j * H, g_eWih_h + (size_t)(H + j) * H,
                  g_eWih_h + (size_t)(2 * H + j) * H, s_x4, lane, gi);
            dot3h(g_eWhh_h + (size_t)j * H, g_eWhh_h + (size_t)(H + j) * H,
                  g_eWhh_h + (size_t)(2 * H + j) * H, s_h4, lane, gh3);
            float rp  = wredu(gi[0] + gh3[0]);
            float zp  = wredu(gi[1] + gh3[1]);
            float anr = wredu(gi[2]);
            float bnr = wredu(gh3[2]);
            if (lane == 0) {
                float r  = sigm(rp + enc_bih[j] + enc_bhh[j]);
                float z  = sigm(zp + enc_bih[H + j] + enc_bhh[H + j]);
                float n  = tanhf(anr + enc_bih[2 * H + j] + r * (bnr + enc_bhh[2 * H + j]));
                float hv = (1.f - z) * n + z * s_h[j];
                hnew[j] = hv;
                g_encout[t * H + j] = hv;
            }
        }
        grid_sync();
        cur ^= 1;
    }

    // ---- P_M (untiled): M[i][k] = comb_W_ctx[i,:] . encout[k,:] ----
    {
        int b  = blockIdx.x;
        int r0 = b * 10 + min(b, 56);
        int nr = 10 + (b < 56 ? 1 : 0);       // 56*11 + 92*10 = 1536 rows
        for (int u = wid; u < nr * 33; u += 32) {
            int lr = u / 33;
            int kc = (u % 33) * 4;            // 0..128
            int i  = r0 + lr;
            const float* w = comb_W + i * (2 * H) + H;
            int k0 = min(kc,     AROWS - 1);
            int k1 = min(kc + 1, AROWS - 1);
            int k2 = min(kc + 2, AROWS - 1);
            int k3 = min(kc + 3, AROWS - 1);
            float s[4];
            dot1536x4(w, g_encout + k0 * H, g_encout + k1 * H,
                         g_encout + k2 * H, g_encout + k3 * H, lane, s);
#pragma unroll
            for (int q = 0; q < 4; q++) s[q] = wredu(s[q]);
            if (lane == 0) {
#pragma unroll
                for (int q = 0; q < 4; q++) {
                    int k = kc + q;
                    if (k < AROWS) g_M[i * MPAD + k] = s[q];
                }
            }
        }
    }
    grid_sync();

    // =========================== DECODER ===========================
    for (int t = 0; t < ML; t++) {
        // --- P1: stage h; gh = Whh.h+bhh (4608) || out logits (128) || attn_h (129) ---
        {
            const float4* h4 = (const float4*)g_h[cur];
            if (tid < 384) s_h4[tid] = __ldcg(h4 + tid);
            __syncthreads();
        }
        for (int task = WGID; task < H3 + HV + AROWS; task += NW) {
            if (task < H3) {
                float s = wredu(dot1536h(g_dWhh_h + (size_t)task * H, s_h4, lane));
                if (lane == 0) g_gh[task] = s + dec_bhh[task];
            } else if (task < H3 + HV) {
                int v = task - H3;
                float s = wredu(dot1536h(g_outW_h + v * H, s_h4, lane));
                if (lane == 0) g_o[v] = s + out_b[v];
            } else {
                int k = task - H3 - HV;
                float s = wredu(dot1536h(g_attnWh_h + k * H, s_h4, lane));
                if (lane == 0) g_attnh[k] = s;
            }
        }
        grid_sync();

        // --- P2: token select, emit row t-1, softmax, x rows ---
        if (wid == 0) {
            int tok; float lse;
            if (t == 0) { tok = 0; lse = 0.f; }
            else {
                float m = -1e30f; int am = HV;
                for (int v = lane; v < HV; v += 32) {
                    float ov = __ldcg(&g_o[v]);
                    if (ov > m) { m = ov; am = v; }
                }
                wargmax(m, am);
                float e = 0.f;
                for (int v = lane; v < HV; v += 32) e += expf(__ldcg(&g_o[v]) - m);
                e = wredu(e);
                lse = m + logf(e);
                tok = am;
            }
            if (lane == 0) { s_tok = tok; s_lse = lse; }
        }
        __syncthreads();
        const int tok = s_tok;
        if (t > 0 && blockIdx.x == 0 && wid == 1) {
            for (int v = lane; v < HV; v += 32) out[(t - 1) * HV + v] = __ldcg(&g_o[v]) - s_lse;
            if (lane == 0 && write_tok) out[ML * HV + (t - 1)] = (float)tok;
        }
        if (wid == 0) {
            const float* aE = g_attE + tok * MPAD;   // write-once: .ca safe
            float m = -1e30f;
            for (int k = lane; k < AROWS; k += 32) m = fmaxf(m, aE[k] + __ldcg(&g_attnh[k]));
#pragma unroll
            for (int o = 16; o; o >>= 1) m = fmaxf(m, __shfl_xor_sync(0xffffffffu, m, o));
            float ssum = 0.f;
            for (int k = lane; k < AROWS; k += 32) {
                float e = expf(aE[k] + __ldcg(&g_attnh[k]) - m);
                s_w[k] = e;
                ssum += e;
            }
            ssum = wredu(ssum);
            if (lane == 0) s_S = ssum;
        }
        __syncthreads();
        {
            const float invS = 1.f / s_S;
            const float* cE = g_combE + tok * H;     // write-once: .ca safe
            for (int i = WGID; i < H; i += NW) {
                const float* Mr = g_M + i * MPAD;    // write-once: .ca safe
                float s = 0.f;
                for (int k = lane; k < AROWS; k += 32) s = fmaf(s_w[k], Mr[k], s);
                s = wredu(s);
                if (lane == 0) g_x[i] = fmaxf(0.f, cE[i] + s * invS);
            }
        }
        grid_sync();

        // --- P3: stage x; gi = dec_Wih @ x, gates -> h' ---
        {
            const float4* x4 = (const float4*)g_x;
            if (tid < 384) s_x4[tid] = __ldcg(x4 + tid);
            __syncthreads();
        }
        {
            float* hnew = g_h[cur ^ 1];
            for (int j = WGID; j < H; j += NW) {
                float gi[3];
                dot3h(g_dWih_h + (size_t)j * H, g_dWih_h + (size_t)(H + j) * H,
                      g_dWih_h + (size_t)(2 * H + j) * H, s_x4, lane, gi);
                float ar = wredu(gi[0]);
                float az = wredu(gi[1]);
                float an = wredu(gi[2]);
                if (lane == 0) {
                    float r = sigm(ar + dec_bih[j]          + __ldcg(&g_gh[j]));
                    float z = sigm(az + dec_bih[H + j]      + __ldcg(&g_gh[H + j]));
                    float n = tanhf(an + dec_bih[2 * H + j] + r * __ldcg(&g_gh[2 * H + j]));
                    hnew[j] = (1.f - z) * n + z * s_h[j];   // hold from P1's staged copy
                }
            }
        }
        grid_sync();
        cur ^= 1;
    }

    // ---- final logits for row ML-1 ----
    {
        const float4* h4 = (const float4*)g_h[cur];
        if (tid < 384) s_h4[tid] = __ldcg(h4 + tid);
        __syncthreads();
        for (int v = WGID; v < HV; v += NW) {
            float s = wredu(dot1536h(g_outW_h + v * H, s_h4, lane));
            if (lane == 0) g_o[v] = s + out_b[v];
        }
    }
    grid_sync();

    if (blockIdx.x == 0 && wid == 0) {
        float m = -1e30f; int am = HV;
        for (int v = lane; v < HV; v += 32) {
            float ov = __ldcg(&g_o[v]);
            if (ov > m) { m = ov; am = v; }
        }
        wargmax(m, am);
        float e = 0.f;
        for (int v = lane; v < HV; v += 32) e += expf(__ldcg(&g_o[v]) - m);
        e = wredu(e);
        float lse = m + logf(e);
        for (int v = lane; v < HV; v += 32) out[(ML - 1) * HV + v] = __ldcg(&g_o[v]) - lse;
        if (lane == 0 && write_tok) out[ML * HV + (ML - 1)] = (float)am;
    }
}

// ---------------- launch ----------------
extern "C" void kernel_launch(void* const* d_in, const int* in_sizes, int n_in,
                              void* d_out, int out_size) {
    const int*   input   = (const int*)  d_in[0];
    const int    L       = in_sizes[0];
    // d_in[1] = max_length scalar (compile-time ML=128)
    const float* emb_enc = (const float*)d_in[2];
    const float* enc_Wih = (const float*)d_in[3];
    const float* enc_Whh = (const float*)d_in[4];
    const float* enc_bih = (const float*)d_in[5];
    const float* enc_bhh = (const float*)d_in[6];
    const float* emb_dec = (const float*)d_in[7];
    const float* attn_W  = (const float*)d_in[8];
    const float* attn_b  = (const float*)d_in[9];
    const float* comb_W  = (const float*)d_in[10];
    const float* comb_b  = (const float*)d_in[11];
    const float* dec_Wih = (const float*)d_in[12];
    const float* dec_Whh = (const float*)d_in[13];
    const float* dec_bih = (const float*)d_in[14];
    const float* dec_bhh = (const float*)d_in[15];
    const float* out_W   = (const float*)d_in[16];
    const float* out_b   = (const float*)d_in[17];

    int write_tok = (out_size >= ML * HV + ML) ? 1 : 0;

    const int nBig = H3 * H / 4;    // float4s per big matrix
    cvt_kernel<<<592, 256>>>((const float4*)enc_Wih, nBig, 0);
    cvt_kernel<<<592, 256>>>((const float4*)enc_Whh, nBig, 1);
    cvt_kernel<<<592, 256>>>((const float4*)dec_Wih, nBig, 2);
    cvt_kernel<<<592, 256>>>((const float4*)dec_Whh, nBig, 3);
    cvt_kernel<<<148, 256>>>((const float4*)out_W, HV * H / 4, 4);
    cvt_attn_kernel<<<148, 256>>>(attn_W);

    seq2seq_kernel<<<GRID, BLOCK>>>(input, L, emb_enc,
                                    enc_bih, enc_bhh,
                                    emb_dec, attn_W, attn_b, comb_W, comb_b,
                                    dec_bih, dec_bhh,
                                    out_b,
                                    (float*)d_out, write_tok);
}